// round 12
// baseline (speedup 1.0000x reference)
#include <cuda_runtime.h>

// CGCoupler: out[n, ro[m]] += x1[n, r1[m]] * x2[n, r2[m]] * cg[m]
//
// SINGLE persistent kernel, one wave.
// Stage 0 (per-CTA, redundant, deterministic): build path tables in smem.
//   Paths = path-major runs (r1/r2/ro consecutive, cg equal) over dense channel
//   dim ns=0..deg-1; run starts partition [0,M) so deg = next_start - start.
//   One block scan -> ordered starts; bin by output base ro_0; canonical in-bin
//   sort (deg desc, r1, r2); per-column {start|ns<<16, eff}. Scratch overlaps
//   the tile buffer region.
// Stage 1 (R5-style mainloop, best measured): x tiles staged 4-rows-interleaved
//   as float4 (gathers = lane-consecutive LDS.128, conflict-free; one load
//   serves 4 rows), register-prefetch pipeline overlaps next tile's LDG with
//   compute, thread owns 2 output columns (fused loop, 8 FMA chains).

#define N_BATCH 16384
#define RPT     4
#define TPB     320
#define NSM     148
#define P_SMEM  512
#define NSORT   512
#define KMAX    4      // supports rep_dim <= KMAX*TPB

__device__ __forceinline__ int block_incl_scan(int v, int tid) {
    __shared__ int ws[32];
    int lane = tid & 31, wid = tid >> 5;
    __syncthreads();
    #pragma unroll
    for (int d = 1; d < 32; d <<= 1) {
        int t = __shfl_up_sync(0xffffffffu, v, d);
        if (lane >= d) v += t;
    }
    if (lane == 31) ws[wid] = v;
    __syncthreads();
    if (wid == 0) {
        int w = (lane < TPB / 32) ? ws[lane] : 0;
        #pragma unroll
        for (int d = 1; d < 32; d <<= 1) {
            int t = __shfl_up_sync(0xffffffffu, w, d);
            if (lane >= d) w += t;
        }
        ws[lane] = w;
    }
    __syncthreads();
    return v + (wid > 0 ? ws[wid - 1] : 0);
}

__global__ void __launch_bounds__(TPB)
cg_kernel(const float* __restrict__ x1, const float* __restrict__ x2,
          float* __restrict__ out,
          const void* r1v, const void* r2v, const void* rov,
          const float* __restrict__ cgv_, int M,
          int rep_dim, int out_dim, int ntiles, int region_bytes) {
    extern __shared__ char smraw[];
    // persistent tables after the buffer/scratch region
    uint4* pts = (uint4*)(smraw + region_bytes);      // P_SMEM paths
    uint2* ci  = (uint2*)(pts + P_SMEM);              // out_dim col info
    // prep scratch (overlaps tile buffers; dead after Stage 0)
    uint4* praw = (uint4*)smraw;                      // NSORT
    int*   sp   = (int*)(praw + NSORT);               // NSORT+1
    int*   pro  = sp + NSORT + 1;                     // NSORT
    int*   cnt  = pro + NSORT;                        // out_dim
    int*   stt  = cnt + out_dim;                      // out_dim
    int*   cur  = stt + out_dim;                      // out_dim
    // tile buffers (Stage 1)
    float4* x1s = (float4*)smraw;                     // rep_dim (4 rows interleaved)
    float4* x2s = x1s + rep_dim;
    __shared__ int s_is64, s_np;

    int tid = threadIdx.x;

    // ================= Stage 0: per-CTA prep (redundant, deterministic) ======
    if (tid < 32) {
        const unsigned* w = (const unsigned*)r1v;
        int nw = M < 512 ? M : 512;
        int bad = 0;
        for (int i = 1 + 2 * tid; i < nw; i += 64) bad |= (w[i] != 0u);
        unsigned any = __ballot_sync(0xffffffffu, bad != 0);
        if (tid == 0) s_is64 = (any == 0u);
    }
    __syncthreads();
    int is64 = s_is64;
    const int*       r132 = (const int*)r1v;  const long long* r164 = (const long long*)r1v;
    const int*       r232 = (const int*)r2v;  const long long* r264 = (const long long*)r2v;
    const int*       ro32 = (const int*)rov;  const long long* ro64 = (const long long*)rov;
    const unsigned*  cgu  = (const unsigned*)cgv_;
    #define IDX1(m) (is64 ? (int)r164[m] : r132[m])
    #define IDX2(m) (is64 ? (int)r264[m] : r232[m])
    #define IDXO(m) (is64 ? (int)ro64[m] : ro32[m])
    #define ISSTART(m) ((m) == 0 || \
        !(IDX1((m) - 1) + 1 == IDX1(m) && IDX2((m) - 1) + 1 == IDX2(m) && \
          IDXO((m) - 1) + 1 == IDXO(m) && cgu[(m) - 1] == cgu[m]))

    // Phase A: ordered compaction of run starts (one block scan)
    {
        int C = (M + TPB - 1) / TPB;
        int beg = tid * C;
        int end = beg + C; if (end > M) end = M;
        int cl = 0;
        for (int m = beg; m < end; m++) cl += ISSTART(m);
        int incl = block_incl_scan(cl, tid);
        int off = incl - cl;
        for (int m = beg; m < end; m++)
            if (ISSTART(m)) { if (off < NSORT) sp[off] = m; off++; }
        if (tid == TPB - 1) s_np = incl;
    }
    __syncthreads();
    int P = s_np;
    if (P > NSORT) P = NSORT;                   // safety; expected P ~ 150
    if (tid == 0) sp[P] = M;
    __syncthreads();

    // Phase B: materialize paths in position order
    for (int p = tid; p < P; p += TPB) {
        int s = sp[p];
        praw[p] = make_uint4((unsigned)IDX1(s), (unsigned)IDX2(s),
                             cgu[s], (unsigned)(sp[p + 1] - s));
        pro[p] = IDXO(s);
    }
    for (int i = tid; i < out_dim; i += TPB) cnt[i] = 0;
    for (int i = tid; i < P_SMEM; i += TPB) pts[i] = make_uint4(0u, 0u, 0u, 0u);
    __syncthreads();

    // Phase C: bin by ro_0, exclusive scan, scatter into pts
    for (int p = tid; p < P; p += TPB) atomicAdd(&cnt[pro[p]], 1);
    __syncthreads();
    {
        int CH = (out_dim + TPB - 1) / TPB;
        int cb = tid * CH;
        int local = 0;
        for (int i = 0; i < CH; i++) { int idx = cb + i; if (idx < out_dim) local += cnt[idx]; }
        int incl = block_incl_scan(local, tid);
        int run = incl - local;
        for (int i = 0; i < CH; i++) {
            int idx = cb + i;
            if (idx < out_dim) { stt[idx] = run; cur[idx] = run; run += cnt[idx]; }
        }
    }
    __syncthreads();
    for (int p = tid; p < P; p += TPB) {
        int pos = atomicAdd(&cur[pro[p]], 1);
        pts[pos] = praw[p];
    }
    __syncthreads();

    // Phase D: canonical in-bin insertion sort (deg DESC, r1 ASC, r2 ASC)
    for (int b = tid; b < out_dim; b += TPB) {
        int c0 = cnt[b];
        if (c0 > 1) {
            int s0 = stt[b];
            for (int i = 1; i < c0; i++) {
                uint4 key = pts[s0 + i];
                int j = i - 1;
                while (j >= 0) {
                    uint4 q = pts[s0 + j];
                    bool keyFirst = (key.w > q.w) ||
                                    (key.w == q.w && (key.x < q.x ||
                                     (key.x == q.x && key.y < q.y)));
                    if (!keyFirst) break;
                    pts[s0 + j + 1] = q;
                    j--;
                }
                pts[s0 + j + 1] = key;
            }
        }
    }
    __syncthreads();

    // Phase E: per-column info
    for (int c = tid; c < out_dim; c += TPB) {
        int b = c;
        while (b >= 0 && cnt[b] == 0) b--;
        uint2 info = make_uint2(0u, 0u);
        if (b >= 0) {
            int c0 = cnt[b], s0 = stt[b], ns = c - b, eff = 0;
            while (eff < c0 && (int)pts[s0 + eff].w > ns) eff++;
            if (eff > 0)
                info = make_uint2((unsigned)s0 | ((unsigned)ns << 16), (unsigned)eff);
        }
        ci[c] = info;
    }
    __syncthreads();   // tables final; scratch region is now the tile buffers
    #undef ISSTART
    #undef IDX1
    #undef IDX2
    #undef IDXO

    // hoisted per-thread column info (tile-invariant)
    int o0 = tid, o1 = tid + TPB;
    uint2 c0 = (o0 < out_dim) ? ci[o0] : make_uint2(0u, 0u);
    uint2 c1 = (o1 < out_dim) ? ci[o1] : make_uint2(0u, 0u);
    int s0 = (int)(c0.x & 0xffffu), ne0 = (int)c0.y; unsigned ns0 = c0.x >> 16;
    int s1 = (int)(c1.x & 0xffffu), ne1 = (int)c1.y; unsigned ns1 = c1.x >> 16;

    // ================= Stage 1: persistent tiles, register-prefetch pipeline ==
    int bid = blockIdx.x, stride = gridDim.x;

    // stage first tile directly
    if (bid < ntiles) {
        const float* a0 = x1 + (size_t)bid * RPT * rep_dim;
        const float* b0 = x2 + (size_t)bid * RPT * rep_dim;
        for (int i = tid; i < rep_dim; i += TPB) {
            x1s[i] = make_float4(a0[i], a0[i + rep_dim],
                                 a0[i + 2 * rep_dim], a0[i + 3 * rep_dim]);
            x2s[i] = make_float4(b0[i], b0[i + rep_dim],
                                 b0[i + 2 * rep_dim], b0[i + 3 * rep_dim]);
        }
    }
    __syncthreads();

    for (int t = bid; t < ntiles; t += stride) {
        int tn = t + stride;
        // prefetch next tile into registers (LDG in flight during compute)
        float4 pa[KMAX], pb[KMAX];
        if (tn < ntiles) {
            const float* a0 = x1 + (size_t)tn * RPT * rep_dim;
            const float* b0 = x2 + (size_t)tn * RPT * rep_dim;
            #pragma unroll
            for (int k = 0; k < KMAX; k++) {
                int i = tid + k * TPB;
                if (i < rep_dim) {
                    pa[k] = make_float4(a0[i], a0[i + rep_dim],
                                        a0[i + 2 * rep_dim], a0[i + 3 * rep_dim]);
                    pb[k] = make_float4(b0[i], b0[i + rep_dim],
                                        b0[i + 2 * rep_dim], b0[i + 3 * rep_dim]);
                }
            }
        }

        // compute current tile
        float4 acc0 = make_float4(0.f, 0.f, 0.f, 0.f);
        float4 acc1 = make_float4(0.f, 0.f, 0.f, 0.f);
        #pragma unroll 2
        for (int j = 0; j < ne0; j++) {
            uint4 p = pts[s0 + j];               // warp-uniform: broadcast
            float cgc = __uint_as_float(p.z);
            float4 A = x1s[p.x + ns0];           // lane-consecutive: conflict-free
            float4 B = x2s[p.y + ns0];
            acc0.x = fmaf(A.x * B.x, cgc, acc0.x);
            acc0.y = fmaf(A.y * B.y, cgc, acc0.y);
            acc0.z = fmaf(A.z * B.z, cgc, acc0.z);
            acc0.w = fmaf(A.w * B.w, cgc, acc0.w);
        }
        #pragma unroll 2
        for (int j = 0; j < ne1; j++) {
            uint4 p = pts[s1 + j];
            float cgc = __uint_as_float(p.z);
            float4 A = x1s[p.x + ns1];
            float4 B = x2s[p.y + ns1];
            acc1.x = fmaf(A.x * B.x, cgc, acc1.x);
            acc1.y = fmaf(A.y * B.y, cgc, acc1.y);
            acc1.z = fmaf(A.z * B.z, cgc, acc1.z);
            acc1.w = fmaf(A.w * B.w, cgc, acc1.w);
        }
        int r = t * RPT;
        if (o0 < out_dim) {
            float* ob = out + (size_t)r * out_dim + o0;
            ob[0] = acc0.x; ob[out_dim] = acc0.y;
            ob[2 * (size_t)out_dim] = acc0.z; ob[3 * (size_t)out_dim] = acc0.w;
        }
        if (o1 < out_dim) {
            float* ob = out + (size_t)r * out_dim + o1;
            ob[0] = acc1.x; ob[out_dim] = acc1.y;
            ob[2 * (size_t)out_dim] = acc1.z; ob[3 * (size_t)out_dim] = acc1.w;
        }
        // generic fallback for out_dim > 2*TPB (not taken for this shape)
        for (int obase = 2 * TPB; obase < out_dim; obase += TPB) {
            int o = obase + tid;
            if (o < out_dim) {
                uint2 c = ci[o];
                int s = (int)(c.x & 0xffffu), ne = (int)c.y;
                unsigned ns = c.x >> 16;
                float4 acc = make_float4(0.f, 0.f, 0.f, 0.f);
                for (int j = 0; j < ne; j++) {
                    uint4 p = pts[s + j];
                    float cgc = __uint_as_float(p.z);
                    float4 A = x1s[p.x + ns];
                    float4 B = x2s[p.y + ns];
                    acc.x = fmaf(A.x * B.x, cgc, acc.x);
                    acc.y = fmaf(A.y * B.y, cgc, acc.y);
                    acc.z = fmaf(A.z * B.z, cgc, acc.z);
                    acc.w = fmaf(A.w * B.w, cgc, acc.w);
                }
                float* ob = out + (size_t)r * out_dim + o;
                ob[0] = acc.x; ob[out_dim] = acc.y;
                ob[2 * (size_t)out_dim] = acc.z; ob[3 * (size_t)out_dim] = acc.w;
            }
        }
        __syncthreads();   // everyone done reading the buffer
        if (tn < ntiles) {
            #pragma unroll
            for (int k = 0; k < KMAX; k++) {
                int i = tid + k * TPB;
                if (i < rep_dim) { x1s[i] = pa[k]; x2s[i] = pb[k]; }
            }
            __syncthreads();   // buffer ready for next tile
        }
    }
}

extern "C" void kernel_launch(void* const* d_in, const int* in_sizes, int n_in,
                              void* d_out, int out_size) {
    const float* x1 = (const float*)d_in[0];
    const float* x2 = (const float*)d_in[1];
    const float* cg = (const float*)d_in[2];
    const void*  r1 = d_in[3];
    const void*  r2 = d_in[4];
    const void*  ro = d_in[5];
    int M = in_sizes[2];
    int rep_dim = in_sizes[0] / N_BATCH;
    int out_dim = out_size / N_BATCH;
    int ntiles  = N_BATCH / RPT;

    // smem: [ region = max(tile buffers, prep scratch) ][ pts ][ ci ]
    size_t bufbytes = (size_t)rep_dim * 32;
    size_t scratch  = (size_t)NSORT * 16 + (size_t)(NSORT + 1) * 4
                    + (size_t)NSORT * 4 + (size_t)3 * out_dim * 4;
    size_t region = bufbytes > scratch ? bufbytes : scratch;
    region = (region + 15) & ~(size_t)15;
    size_t smem = region + (size_t)P_SMEM * 16 + (size_t)out_dim * 8;

    cudaFuncSetAttribute(cg_kernel,
                         cudaFuncAttributeMaxDynamicSharedMemorySize, 220 * 1024);
    // one full wave, no tail: grid = resident CTAs
    int bpm = 0;
    cudaOccupancyMaxActiveBlocksPerMultiprocessor(&bpm, cg_kernel, TPB, smem);
    if (bpm < 1) bpm = 1;
    int grid = bpm * NSM;
    if (grid > ntiles) grid = ntiles;
    cg_kernel<<<grid, TPB, smem>>>(x1, x2, (float*)d_out, r1, r2, ro, cg, M,
                                   rep_dim, out_dim, ntiles, (int)region);
}

// round 13
// speedup vs baseline: 1.4075x; 1.4075x over previous
#include <cuda_runtime.h>

// CGCoupler: out[n, ro[m]] += x1[n, r1[m]] * x2[n, r2[m]] * cg[m]
//
// SINGLE persistent kernel, one wave, __launch_bounds__(320,3) (the R12 regs=96
// blowup came from leaving the occupancy clause off).
// Stage 0 (per-CTA, redundant, deterministic): build path tables in smem.
//   Paths = path-major runs (r1/r2/ro consecutive, cg equal) over dense channel
//   dim ns=0..deg-1; run starts partition [0,M) so deg = next_start - start.
//   One block scan -> ordered starts; bin by output base ro_0; canonical in-bin
//   sort (deg desc, r1, r2); per-column {start|ns<<16, eff}. Scratch overlaps
//   the tile buffer region.
// Stage 1 (R5-style mainloop, best measured 43.3us): x tiles staged
//   4-rows-interleaved as float4 (gathers = lane-consecutive LDS.128,
//   conflict-free; one load serves 4 rows), register-prefetch pipeline (KMAX=2,
//   sized exactly for rep_dim<=640) overlaps next tile's LDG with compute,
//   thread owns 2 output columns (fused loop, 8 independent FMA chains).

#define N_BATCH 16384
#define RPT     4
#define TPB     320
#define OCC     3
#define NSM     148
#define P_SMEM  512
#define NSORT   512
#define KMAX    2      // prefetch path covers rep_dim <= KMAX*TPB

__device__ __forceinline__ int block_incl_scan(int v, int tid) {
    __shared__ int ws[32];
    int lane = tid & 31, wid = tid >> 5;
    __syncthreads();
    #pragma unroll
    for (int d = 1; d < 32; d <<= 1) {
        int t = __shfl_up_sync(0xffffffffu, v, d);
        if (lane >= d) v += t;
    }
    if (lane == 31) ws[wid] = v;
    __syncthreads();
    if (wid == 0) {
        int w = (lane < TPB / 32) ? ws[lane] : 0;
        #pragma unroll
        for (int d = 1; d < 32; d <<= 1) {
            int t = __shfl_up_sync(0xffffffffu, w, d);
            if (lane >= d) w += t;
        }
        ws[lane] = w;
    }
    __syncthreads();
    return v + (wid > 0 ? ws[wid - 1] : 0);
}

__global__ void __launch_bounds__(TPB, OCC)
cg_kernel(const float* __restrict__ x1, const float* __restrict__ x2,
          float* __restrict__ out,
          const void* r1v, const void* r2v, const void* rov,
          const float* __restrict__ cgv_, int M,
          int rep_dim, int out_dim, int ntiles, int region_bytes) {
    extern __shared__ char smraw[];
    // persistent tables after the buffer/scratch region
    uint4* pts = (uint4*)(smraw + region_bytes);      // P_SMEM paths
    uint2* ci  = (uint2*)(pts + P_SMEM);              // out_dim col info
    // prep scratch (overlaps tile buffers; dead after Stage 0)
    uint4* praw = (uint4*)smraw;                      // NSORT
    int*   sp   = (int*)(praw + NSORT);               // NSORT+1
    int*   pro  = sp + NSORT + 1;                     // NSORT
    int*   cnt  = pro + NSORT;                        // out_dim
    int*   stt  = cnt + out_dim;                      // out_dim
    int*   cur  = stt + out_dim;                      // out_dim
    // tile buffers (Stage 1)
    float4* x1s = (float4*)smraw;                     // rep_dim (4 rows interleaved)
    float4* x2s = x1s + rep_dim;
    __shared__ int s_is64, s_np;

    int tid = threadIdx.x;

    // ================= Stage 0: per-CTA prep (redundant, deterministic) ======
    if (tid < 32) {
        const unsigned* w = (const unsigned*)r1v;
        int nw = M < 512 ? M : 512;
        int bad = 0;
        for (int i = 1 + 2 * tid; i < nw; i += 64) bad |= (w[i] != 0u);
        unsigned any = __ballot_sync(0xffffffffu, bad != 0);
        if (tid == 0) s_is64 = (any == 0u);
    }
    __syncthreads();
    int is64 = s_is64;
    const int*       r132 = (const int*)r1v;  const long long* r164 = (const long long*)r1v;
    const int*       r232 = (const int*)r2v;  const long long* r264 = (const long long*)r2v;
    const int*       ro32 = (const int*)rov;  const long long* ro64 = (const long long*)rov;
    const unsigned*  cgu  = (const unsigned*)cgv_;
    #define IDX1(m) (is64 ? (int)r164[m] : r132[m])
    #define IDX2(m) (is64 ? (int)r264[m] : r232[m])
    #define IDXO(m) (is64 ? (int)ro64[m] : ro32[m])
    #define ISSTART(m) ((m) == 0 || \
        !(IDX1((m) - 1) + 1 == IDX1(m) && IDX2((m) - 1) + 1 == IDX2(m) && \
          IDXO((m) - 1) + 1 == IDXO(m) && cgu[(m) - 1] == cgu[m]))

    // Phase A: ordered compaction of run starts (one block scan)
    {
        int C = (M + TPB - 1) / TPB;
        int beg = tid * C;
        int end = beg + C; if (end > M) end = M;
        int cl = 0;
        for (int m = beg; m < end; m++) cl += ISSTART(m);
        int incl = block_incl_scan(cl, tid);
        int off = incl - cl;
        for (int m = beg; m < end; m++)
            if (ISSTART(m)) { if (off < NSORT) sp[off] = m; off++; }
        if (tid == TPB - 1) s_np = incl;
    }
    __syncthreads();
    int P = s_np;
    if (P > NSORT) P = NSORT;                   // safety; expected P ~ 150
    if (tid == 0) sp[P] = M;
    __syncthreads();

    // Phase B: materialize paths in position order
    for (int p = tid; p < P; p += TPB) {
        int s = sp[p];
        praw[p] = make_uint4((unsigned)IDX1(s), (unsigned)IDX2(s),
                             cgu[s], (unsigned)(sp[p + 1] - s));
        pro[p] = IDXO(s);
    }
    for (int i = tid; i < out_dim; i += TPB) cnt[i] = 0;
    for (int i = tid; i < P_SMEM; i += TPB) pts[i] = make_uint4(0u, 0u, 0u, 0u);
    __syncthreads();

    // Phase C: bin by ro_0, exclusive scan, scatter into pts
    for (int p = tid; p < P; p += TPB) atomicAdd(&cnt[pro[p]], 1);
    __syncthreads();
    {
        int CH = (out_dim + TPB - 1) / TPB;
        int cb = tid * CH;
        int local = 0;
        for (int i = 0; i < CH; i++) { int idx = cb + i; if (idx < out_dim) local += cnt[idx]; }
        int incl = block_incl_scan(local, tid);
        int run = incl - local;
        for (int i = 0; i < CH; i++) {
            int idx = cb + i;
            if (idx < out_dim) { stt[idx] = run; cur[idx] = run; run += cnt[idx]; }
        }
    }
    __syncthreads();
    for (int p = tid; p < P; p += TPB) {
        int pos = atomicAdd(&cur[pro[p]], 1);
        pts[pos] = praw[p];
    }
    __syncthreads();

    // Phase D: canonical in-bin insertion sort (deg DESC, r1 ASC, r2 ASC)
    for (int b = tid; b < out_dim; b += TPB) {
        int c0 = cnt[b];
        if (c0 > 1) {
            int s0 = stt[b];
            for (int i = 1; i < c0; i++) {
                uint4 key = pts[s0 + i];
                int j = i - 1;
                while (j >= 0) {
                    uint4 q = pts[s0 + j];
                    bool keyFirst = (key.w > q.w) ||
                                    (key.w == q.w && (key.x < q.x ||
                                     (key.x == q.x && key.y < q.y)));
                    if (!keyFirst) break;
                    pts[s0 + j + 1] = q;
                    j--;
                }
                pts[s0 + j + 1] = key;
            }
        }
    }
    __syncthreads();

    // Phase E: per-column info
    for (int c = tid; c < out_dim; c += TPB) {
        int b = c;
        while (b >= 0 && cnt[b] == 0) b--;
        uint2 info = make_uint2(0u, 0u);
        if (b >= 0) {
            int c0 = cnt[b], s0 = stt[b], ns = c - b, eff = 0;
            while (eff < c0 && (int)pts[s0 + eff].w > ns) eff++;
            if (eff > 0)
                info = make_uint2((unsigned)s0 | ((unsigned)ns << 16), (unsigned)eff);
        }
        ci[c] = info;
    }
    __syncthreads();   // tables final; scratch region is now the tile buffers
    #undef ISSTART
    #undef IDX1
    #undef IDX2
    #undef IDXO

    // hoisted per-thread column info (tile-invariant)
    int o0 = tid, o1 = tid + TPB;
    uint2 c0 = (o0 < out_dim) ? ci[o0] : make_uint2(0u, 0u);
    uint2 c1 = (o1 < out_dim) ? ci[o1] : make_uint2(0u, 0u);
    int s0 = (int)(c0.x & 0xffffu), ne0 = (int)c0.y; unsigned ns0 = c0.x >> 16;
    int s1 = (int)(c1.x & 0xffffu), ne1 = (int)c1.y; unsigned ns1 = c1.x >> 16;

    // ================= Stage 1: persistent tiles, register-prefetch pipeline ==
    int bid = blockIdx.x, stride = gridDim.x;
    bool use_pf = (rep_dim <= KMAX * TPB);

    // stage first tile directly
    if (bid < ntiles) {
        const float* a0 = x1 + (size_t)bid * RPT * rep_dim;
        const float* b0 = x2 + (size_t)bid * RPT * rep_dim;
        for (int i = tid; i < rep_dim; i += TPB) {
            x1s[i] = make_float4(a0[i], a0[i + rep_dim],
                                 a0[i + 2 * rep_dim], a0[i + 3 * rep_dim]);
            x2s[i] = make_float4(b0[i], b0[i + rep_dim],
                                 b0[i + 2 * rep_dim], b0[i + 3 * rep_dim]);
        }
    }
    __syncthreads();

    for (int t = bid; t < ntiles; t += stride) {
        int tn = t + stride;
        // prefetch next tile into registers (LDG in flight during compute)
        float4 pa[KMAX], pb[KMAX];
        if (use_pf && tn < ntiles) {
            const float* a0 = x1 + (size_t)tn * RPT * rep_dim;
            const float* b0 = x2 + (size_t)tn * RPT * rep_dim;
            #pragma unroll
            for (int k = 0; k < KMAX; k++) {
                int i = tid + k * TPB;
                if (i < rep_dim) {
                    pa[k] = make_float4(a0[i], a0[i + rep_dim],
                                        a0[i + 2 * rep_dim], a0[i + 3 * rep_dim]);
                    pb[k] = make_float4(b0[i], b0[i + rep_dim],
                                        b0[i + 2 * rep_dim], b0[i + 3 * rep_dim]);
                }
            }
        }

        // compute current tile
        float4 acc0 = make_float4(0.f, 0.f, 0.f, 0.f);
        float4 acc1 = make_float4(0.f, 0.f, 0.f, 0.f);
        #pragma unroll 2
        for (int j = 0; j < ne0; j++) {
            uint4 p = pts[s0 + j];               // warp-uniform: broadcast
            float cgc = __uint_as_float(p.z);
            float4 A = x1s[p.x + ns0];           // lane-consecutive: conflict-free
            float4 B = x2s[p.y + ns0];
            acc0.x = fmaf(A.x * B.x, cgc, acc0.x);
            acc0.y = fmaf(A.y * B.y, cgc, acc0.y);
            acc0.z = fmaf(A.z * B.z, cgc, acc0.z);
            acc0.w = fmaf(A.w * B.w, cgc, acc0.w);
        }
        #pragma unroll 2
        for (int j = 0; j < ne1; j++) {
            uint4 p = pts[s1 + j];
            float cgc = __uint_as_float(p.z);
            float4 A = x1s[p.x + ns1];
            float4 B = x2s[p.y + ns1];
            acc1.x = fmaf(A.x * B.x, cgc, acc1.x);
            acc1.y = fmaf(A.y * B.y, cgc, acc1.y);
            acc1.z = fmaf(A.z * B.z, cgc, acc1.z);
            acc1.w = fmaf(A.w * B.w, cgc, acc1.w);
        }
        int r = t * RPT;
        if (o0 < out_dim) {
            float* ob = out + (size_t)r * out_dim + o0;
            ob[0] = acc0.x; ob[out_dim] = acc0.y;
            ob[2 * (size_t)out_dim] = acc0.z; ob[3 * (size_t)out_dim] = acc0.w;
        }
        if (o1 < out_dim) {
            float* ob = out + (size_t)r * out_dim + o1;
            ob[0] = acc1.x; ob[out_dim] = acc1.y;
            ob[2 * (size_t)out_dim] = acc1.z; ob[3 * (size_t)out_dim] = acc1.w;
        }
        // generic fallback for out_dim > 2*TPB (not taken for this shape)
        for (int obase = 2 * TPB; obase < out_dim; obase += TPB) {
            int o = obase + tid;
            if (o < out_dim) {
                uint2 c = ci[o];
                int s = (int)(c.x & 0xffffu), ne = (int)c.y;
                unsigned ns = c.x >> 16;
                float4 acc = make_float4(0.f, 0.f, 0.f, 0.f);
                for (int j = 0; j < ne; j++) {
                    uint4 p = pts[s + j];
                    float cgc = __uint_as_float(p.z);
                    float4 A = x1s[p.x + ns];
                    float4 B = x2s[p.y + ns];
                    acc.x = fmaf(A.x * B.x, cgc, acc.x);
                    acc.y = fmaf(A.y * B.y, cgc, acc.y);
                    acc.z = fmaf(A.z * B.z, cgc, acc.z);
                    acc.w = fmaf(A.w * B.w, cgc, acc.w);
                }
                float* ob = out + (size_t)r * out_dim + o;
                ob[0] = acc.x; ob[out_dim] = acc.y;
                ob[2 * (size_t)out_dim] = acc.z; ob[3 * (size_t)out_dim] = acc.w;
            }
        }
        __syncthreads();   // everyone done reading the buffer
        if (tn < ntiles) {
            if (use_pf) {
                #pragma unroll
                for (int k = 0; k < KMAX; k++) {
                    int i = tid + k * TPB;
                    if (i < rep_dim) { x1s[i] = pa[k]; x2s[i] = pb[k]; }
                }
            } else {
                const float* a0 = x1 + (size_t)tn * RPT * rep_dim;
                const float* b0 = x2 + (size_t)tn * RPT * rep_dim;
                for (int i = tid; i < rep_dim; i += TPB) {
                    x1s[i] = make_float4(a0[i], a0[i + rep_dim],
                                         a0[i + 2 * rep_dim], a0[i + 3 * rep_dim]);
                    x2s[i] = make_float4(b0[i], b0[i + rep_dim],
                                         b0[i + 2 * rep_dim], b0[i + 3 * rep_dim]);
                }
            }
            __syncthreads();   // buffer ready for next tile
        }
    }
}

extern "C" void kernel_launch(void* const* d_in, const int* in_sizes, int n_in,
                              void* d_out, int out_size) {
    const float* x1 = (const float*)d_in[0];
    const float* x2 = (const float*)d_in[1];
    const float* cg = (const float*)d_in[2];
    const void*  r1 = d_in[3];
    const void*  r2 = d_in[4];
    const void*  ro = d_in[5];
    int M = in_sizes[2];
    int rep_dim = in_sizes[0] / N_BATCH;
    int out_dim = out_size / N_BATCH;
    int ntiles  = N_BATCH / RPT;

    // smem: [ region = max(tile buffers, prep scratch) ][ pts ][ ci ]
    size_t bufbytes = (size_t)rep_dim * 32;
    size_t scratch  = (size_t)NSORT * 16 + (size_t)(NSORT + 1) * 4
                    + (size_t)NSORT * 4 + (size_t)3 * out_dim * 4;
    size_t region = bufbytes > scratch ? bufbytes : scratch;
    region = (region + 15) & ~(size_t)15;
    size_t smem = region + (size_t)P_SMEM * 16 + (size_t)out_dim * 8;

    cudaFuncSetAttribute(cg_kernel,
                         cudaFuncAttributeMaxDynamicSharedMemorySize, 220 * 1024);
    // one full wave, no tail: grid = resident CTAs
    int bpm = 0;
    cudaOccupancyMaxActiveBlocksPerMultiprocessor(&bpm, cg_kernel, TPB, smem);
    if (bpm < 1) bpm = 1;
    int grid = bpm * NSM;
    if (grid > ntiles) grid = ntiles;
    cg_kernel<<<grid, TPB, smem>>>(x1, x2, (float*)d_out, r1, r2, ro, cg, M,
                                   rep_dim, out_dim, ntiles, (int)region);
}

// round 14
// speedup vs baseline: 1.6754x; 1.1904x over previous
#include <cuda_runtime.h>

// CGCoupler: out[n, ro[m]] += x1[n, r1[m]] * x2[n, r2[m]] * cg[m]
//
// SINGLE persistent kernel, one wave, __launch_bounds__(320,3).
// Stage 0 (per-CTA, redundant, deterministic): build path tables in smem.
//   R13 lesson: Phase A MUST be lane-coalesced -- thread-contiguous chunk
//   scanning cost ~38K L1 wavefronts/CTA (32 lines per warp-load) and
//   dominated the kernel. Now: round k, thread tid handles m = k*TPB+tid
//   (lane-consecutive loads), indices read as 32-bit low words (stride 2 for
//   int64). Ordered compaction via one block scan per round (15 rounds,
//   ~300 cyc each). Then bin by output base ro_0, canonical in-bin sort
//   (deg desc, r1, r2), per-column {start|ns<<16, eff}. Scratch overlaps
//   the tile buffers.
// Stage 1 (R5 mainloop, best measured 43.3us): x tiles staged 4-rows-
//   interleaved as float4 (gathers = lane-consecutive LDS.128, conflict-free),
//   register-prefetch pipeline (KMAX=2) overlaps next tile's LDG with compute,
//   thread owns 2 output columns (fused loop, 8 independent FMA chains).

#define N_BATCH 16384
#define RPT     4
#define TPB     320
#define OCC     3
#define NSM     148
#define P_SMEM  512
#define NSORT   512
#define KMAX    2      // prefetch path covers rep_dim <= KMAX*TPB

__device__ __forceinline__ int block_incl_scan(int v, int tid) {
    __shared__ int ws[32];
    int lane = tid & 31, wid = tid >> 5;
    __syncthreads();
    #pragma unroll
    for (int d = 1; d < 32; d <<= 1) {
        int t = __shfl_up_sync(0xffffffffu, v, d);
        if (lane >= d) v += t;
    }
    if (lane == 31) ws[wid] = v;
    __syncthreads();
    if (wid == 0) {
        int w = (lane < TPB / 32) ? ws[lane] : 0;
        #pragma unroll
        for (int d = 1; d < 32; d <<= 1) {
            int t = __shfl_up_sync(0xffffffffu, w, d);
            if (lane >= d) w += t;
        }
        ws[lane] = w;
    }
    __syncthreads();
    return v + (wid > 0 ? ws[wid - 1] : 0);
}

__global__ void __launch_bounds__(TPB, OCC)
cg_kernel(const float* __restrict__ x1, const float* __restrict__ x2,
          float* __restrict__ out,
          const void* r1v, const void* r2v, const void* rov,
          const float* __restrict__ cgv_, int M,
          int rep_dim, int out_dim, int ntiles, int region_bytes) {
    extern __shared__ char smraw[];
    // persistent tables after the buffer/scratch region
    uint4* pts = (uint4*)(smraw + region_bytes);      // P_SMEM paths
    uint2* ci  = (uint2*)(pts + P_SMEM);              // out_dim col info
    // prep scratch (overlaps tile buffers; dead after Stage 0)
    uint4* praw = (uint4*)smraw;                      // NSORT
    int*   sp   = (int*)(praw + NSORT);               // NSORT+1
    int*   pro  = sp + NSORT + 1;                     // NSORT
    int*   cnt  = pro + NSORT;                        // out_dim
    int*   stt  = cnt + out_dim;                      // out_dim
    int*   cur  = stt + out_dim;                      // out_dim
    // tile buffers (Stage 1)
    float4* x1s = (float4*)smraw;                     // rep_dim (4 rows interleaved)
    float4* x2s = x1s + rep_dim;
    __shared__ int s_is64, s_carry;

    int tid = threadIdx.x;

    // ================= Stage 0: per-CTA prep (redundant, deterministic) ======
    if (tid < 32) {
        const unsigned* w = (const unsigned*)r1v;
        int nw = M < 512 ? M : 512;
        int bad = 0;
        for (int i = 1 + 2 * tid; i < nw; i += 64) bad |= (w[i] != 0u);
        unsigned any = __ballot_sync(0xffffffffu, bad != 0);
        if (tid == 0) { s_is64 = (any == 0u); s_carry = 0; }
    }
    __syncthreads();
    // 32-bit low-word access (values are small; little-endian): stride 2 if int64
    int sh = s_is64 ? 1 : 0;
    const int*      A1  = (const int*)r1v;
    const int*      A2  = (const int*)r2v;
    const int*      AO  = (const int*)rov;
    const unsigned* cgu = (const unsigned*)cgv_;
    #define IDX1(m) A1[(m) << sh]
    #define IDX2(m) A2[(m) << sh]
    #define IDXO(m) AO[(m) << sh]
    #define ISSTART(m) ((m) == 0 || \
        !(IDX1((m) - 1) + 1 == IDX1(m) && IDX2((m) - 1) + 1 == IDX2(m) && \
          IDXO((m) - 1) + 1 == IDXO(m) && cgu[(m) - 1] == cgu[m]))

    // Phase A: ordered compaction of run starts -- COALESCED rounds:
    // round base, thread tid handles m = base + tid (lane-consecutive loads).
    for (int base = 0; base < M; base += TPB) {
        int m = base + tid;
        int f = (m < M) ? (ISSTART(m) ? 1 : 0) : 0;
        int incl = block_incl_scan(f, tid);      // starts & ends with syncs
        int carry = s_carry;
        if (f) {
            int pid = carry + incl - 1;
            if (pid < NSORT) sp[pid] = m;
        }
        __syncthreads();
        if (tid == TPB - 1) s_carry = carry + incl;
        __syncthreads();
    }
    int P = s_carry;
    if (P > NSORT) P = NSORT;                   // safety; expected P ~ 150
    if (tid == 0) sp[P] = M;
    __syncthreads();

    // Phase B: materialize paths in position order (scattered but tiny: P reads)
    for (int p = tid; p < P; p += TPB) {
        int s = sp[p];
        praw[p] = make_uint4((unsigned)IDX1(s), (unsigned)IDX2(s),
                             cgu[s], (unsigned)(sp[p + 1] - s));
        pro[p] = IDXO(s);
    }
    for (int i = tid; i < out_dim; i += TPB) cnt[i] = 0;
    for (int i = tid; i < P_SMEM; i += TPB) pts[i] = make_uint4(0u, 0u, 0u, 0u);
    __syncthreads();

    // Phase C: bin by ro_0, exclusive scan, scatter into pts
    for (int p = tid; p < P; p += TPB) atomicAdd(&cnt[pro[p]], 1);
    __syncthreads();
    {
        int CH = (out_dim + TPB - 1) / TPB;
        int cb = tid * CH;
        int local = 0;
        for (int i = 0; i < CH; i++) { int idx = cb + i; if (idx < out_dim) local += cnt[idx]; }
        int incl = block_incl_scan(local, tid);
        int run = incl - local;
        for (int i = 0; i < CH; i++) {
            int idx = cb + i;
            if (idx < out_dim) { stt[idx] = run; cur[idx] = run; run += cnt[idx]; }
        }
    }
    __syncthreads();
    for (int p = tid; p < P; p += TPB) {
        int pos = atomicAdd(&cur[pro[p]], 1);
        pts[pos] = praw[p];
    }
    __syncthreads();

    // Phase D: canonical in-bin insertion sort (deg DESC, r1 ASC, r2 ASC)
    for (int b = tid; b < out_dim; b += TPB) {
        int c0 = cnt[b];
        if (c0 > 1) {
            int s0 = stt[b];
            for (int i = 1; i < c0; i++) {
                uint4 key = pts[s0 + i];
                int j = i - 1;
                while (j >= 0) {
                    uint4 q = pts[s0 + j];
                    bool keyFirst = (key.w > q.w) ||
                                    (key.w == q.w && (key.x < q.x ||
                                     (key.x == q.x && key.y < q.y)));
                    if (!keyFirst) break;
                    pts[s0 + j + 1] = q;
                    j--;
                }
                pts[s0 + j + 1] = key;
            }
        }
    }
    __syncthreads();

    // Phase E: per-column info
    for (int c = tid; c < out_dim; c += TPB) {
        int b = c;
        while (b >= 0 && cnt[b] == 0) b--;
        uint2 info = make_uint2(0u, 0u);
        if (b >= 0) {
            int c0 = cnt[b], s0 = stt[b], ns = c - b, eff = 0;
            while (eff < c0 && (int)pts[s0 + eff].w > ns) eff++;
            if (eff > 0)
                info = make_uint2((unsigned)s0 | ((unsigned)ns << 16), (unsigned)eff);
        }
        ci[c] = info;
    }
    __syncthreads();   // tables final; scratch region is now the tile buffers
    #undef ISSTART
    #undef IDX1
    #undef IDX2
    #undef IDXO

    // hoisted per-thread column info (tile-invariant)
    int o0 = tid, o1 = tid + TPB;
    uint2 c0 = (o0 < out_dim) ? ci[o0] : make_uint2(0u, 0u);
    uint2 c1 = (o1 < out_dim) ? ci[o1] : make_uint2(0u, 0u);
    int s0 = (int)(c0.x & 0xffffu), ne0 = (int)c0.y; unsigned ns0 = c0.x >> 16;
    int s1 = (int)(c1.x & 0xffffu), ne1 = (int)c1.y; unsigned ns1 = c1.x >> 16;

    // ================= Stage 1: persistent tiles, register-prefetch pipeline ==
    int bid = blockIdx.x, stride = gridDim.x;
    bool use_pf = (rep_dim <= KMAX * TPB);

    // stage first tile directly
    if (bid < ntiles) {
        const float* a0 = x1 + (size_t)bid * RPT * rep_dim;
        const float* b0 = x2 + (size_t)bid * RPT * rep_dim;
        for (int i = tid; i < rep_dim; i += TPB) {
            x1s[i] = make_float4(a0[i], a0[i + rep_dim],
                                 a0[i + 2 * rep_dim], a0[i + 3 * rep_dim]);
            x2s[i] = make_float4(b0[i], b0[i + rep_dim],
                                 b0[i + 2 * rep_dim], b0[i + 3 * rep_dim]);
        }
    }
    __syncthreads();

    for (int t = bid; t < ntiles; t += stride) {
        int tn = t + stride;
        // prefetch next tile into registers (LDG in flight during compute)
        float4 pa[KMAX], pb[KMAX];
        if (use_pf && tn < ntiles) {
            const float* a0 = x1 + (size_t)tn * RPT * rep_dim;
            const float* b0 = x2 + (size_t)tn * RPT * rep_dim;
            #pragma unroll
            for (int k = 0; k < KMAX; k++) {
                int i = tid + k * TPB;
                if (i < rep_dim) {
                    pa[k] = make_float4(a0[i], a0[i + rep_dim],
                                        a0[i + 2 * rep_dim], a0[i + 3 * rep_dim]);
                    pb[k] = make_float4(b0[i], b0[i + rep_dim],
                                        b0[i + 2 * rep_dim], b0[i + 3 * rep_dim]);
                }
            }
        }

        // compute current tile
        float4 acc0 = make_float4(0.f, 0.f, 0.f, 0.f);
        float4 acc1 = make_float4(0.f, 0.f, 0.f, 0.f);
        #pragma unroll 2
        for (int j = 0; j < ne0; j++) {
            uint4 p = pts[s0 + j];               // warp-uniform: broadcast
            float cgc = __uint_as_float(p.z);
            float4 A = x1s[p.x + ns0];           // lane-consecutive: conflict-free
            float4 B = x2s[p.y + ns0];
            acc0.x = fmaf(A.x * B.x, cgc, acc0.x);
            acc0.y = fmaf(A.y * B.y, cgc, acc0.y);
            acc0.z = fmaf(A.z * B.z, cgc, acc0.z);
            acc0.w = fmaf(A.w * B.w, cgc, acc0.w);
        }
        #pragma unroll 2
        for (int j = 0; j < ne1; j++) {
            uint4 p = pts[s1 + j];
            float cgc = __uint_as_float(p.z);
            float4 A = x1s[p.x + ns1];
            float4 B = x2s[p.y + ns1];
            acc1.x = fmaf(A.x * B.x, cgc, acc1.x);
            acc1.y = fmaf(A.y * B.y, cgc, acc1.y);
            acc1.z = fmaf(A.z * B.z, cgc, acc1.z);
            acc1.w = fmaf(A.w * B.w, cgc, acc1.w);
        }
        int r = t * RPT;
        if (o0 < out_dim) {
            float* ob = out + (size_t)r * out_dim + o0;
            ob[0] = acc0.x; ob[out_dim] = acc0.y;
            ob[2 * (size_t)out_dim] = acc0.z; ob[3 * (size_t)out_dim] = acc0.w;
        }
        if (o1 < out_dim) {
            float* ob = out + (size_t)r * out_dim + o1;
            ob[0] = acc1.x; ob[out_dim] = acc1.y;
            ob[2 * (size_t)out_dim] = acc1.z; ob[3 * (size_t)out_dim] = acc1.w;
        }
        // generic fallback for out_dim > 2*TPB (not taken for this shape)
        for (int obase = 2 * TPB; obase < out_dim; obase += TPB) {
            int o = obase + tid;
            if (o < out_dim) {
                uint2 c = ci[o];
                int s = (int)(c.x & 0xffffu), ne = (int)c.y;
                unsigned ns = c.x >> 16;
                float4 acc = make_float4(0.f, 0.f, 0.f, 0.f);
                for (int j = 0; j < ne; j++) {
                    uint4 p = pts[s + j];
                    float cgc = __uint_as_float(p.z);
                    float4 A = x1s[p.x + ns];
                    float4 B = x2s[p.y + ns];
                    acc.x = fmaf(A.x * B.x, cgc, acc.x);
                    acc.y = fmaf(A.y * B.y, cgc, acc.y);
                    acc.z = fmaf(A.z * B.z, cgc, acc.z);
                    acc.w = fmaf(A.w * B.w, cgc, acc.w);
                }
                float* ob = out + (size_t)r * out_dim + o;
                ob[0] = acc.x; ob[out_dim] = acc.y;
                ob[2 * (size_t)out_dim] = acc.z; ob[3 * (size_t)out_dim] = acc.w;
            }
        }
        __syncthreads();   // everyone done reading the buffer
        if (tn < ntiles) {
            if (use_pf) {
                #pragma unroll
                for (int k = 0; k < KMAX; k++) {
                    int i = tid + k * TPB;
                    if (i < rep_dim) { x1s[i] = pa[k]; x2s[i] = pb[k]; }
                }
            } else {
                const float* a0 = x1 + (size_t)tn * RPT * rep_dim;
                const float* b0 = x2 + (size_t)tn * RPT * rep_dim;
                for (int i = tid; i < rep_dim; i += TPB) {
                    x1s[i] = make_float4(a0[i], a0[i + rep_dim],
                                         a0[i + 2 * rep_dim], a0[i + 3 * rep_dim]);
                    x2s[i] = make_float4(b0[i], b0[i + rep_dim],
                                         b0[i + 2 * rep_dim], b0[i + 3 * rep_dim]);
                }
            }
            __syncthreads();   // buffer ready for next tile
        }
    }
}

extern "C" void kernel_launch(void* const* d_in, const int* in_sizes, int n_in,
                              void* d_out, int out_size) {
    const float* x1 = (const float*)d_in[0];
    const float* x2 = (const float*)d_in[1];
    const float* cg = (const float*)d_in[2];
    const void*  r1 = d_in[3];
    const void*  r2 = d_in[4];
    const void*  ro = d_in[5];
    int M = in_sizes[2];
    int rep_dim = in_sizes[0] / N_BATCH;
    int out_dim = out_size / N_BATCH;
    int ntiles  = N_BATCH / RPT;

    // smem: [ region = max(tile buffers, prep scratch) ][ pts ][ ci ]
    size_t bufbytes = (size_t)rep_dim * 32;
    size_t scratch  = (size_t)NSORT * 16 + (size_t)(NSORT + 1) * 4
                    + (size_t)NSORT * 4 + (size_t)3 * out_dim * 4;
    size_t region = bufbytes > scratch ? bufbytes : scratch;
    region = (region + 15) & ~(size_t)15;
    size_t smem = region + (size_t)P_SMEM * 16 + (size_t)out_dim * 8;

    cudaFuncSetAttribute(cg_kernel,
                         cudaFuncAttributeMaxDynamicSharedMemorySize, 220 * 1024);
    // one full wave, no tail: grid = resident CTAs
    int bpm = 0;
    cudaOccupancyMaxActiveBlocksPerMultiprocessor(&bpm, cg_kernel, TPB, smem);
    if (bpm < 1) bpm = 1;
    int grid = bpm * NSM;
    if (grid > ntiles) grid = ntiles;
    cg_kernel<<<grid, TPB, smem>>>(x1, x2, (float*)d_out, r1, r2, ro, cg, M,
                                   rep_dim, out_dim, ntiles, (int)region);
}

// round 15
// speedup vs baseline: 2.2796x; 1.3607x over previous
#include <cuda_runtime.h>

// CGCoupler: out[n, ro[m]] += x1[n, r1[m]] * x2[n, r2[m]] * cg[m]
//
// Two kernels -- each the best-measured variant of its half:
// prep (1 CTA, 1024 thr, smem-resident, COALESCED Phase A): paths are
//   path-major runs (r1/r2/ro consecutive, cg equal) over dense channel dim
//   ns=0..deg-1; run starts partition [0,M) so deg = next_start - start.
//   Phase A: rounds of lane-consecutive loads (m = base + tid) + one block
//   scan per round -> ordered start positions (deterministic). Then bin by
//   output base ro_0, exclusive scan, scatter, canonical in-bin insertion
//   sort (deg desc, r1 asc, r2 asc) -- all in shared memory -- and write out
//   g_paths (zero-padded to P_SMEM) + per-column g_colinfo {start|ns<<16, eff}.
// couple (R5 exact, measured 43.3us): 16 rows per CTA in 4-row subtiles,
//   x tiles staged 4-rows-interleaved as float4 (gathers = lane-consecutive
//   LDS.128, conflict-free), KMAX=4 register-prefetch pipeline overlaps next
//   subtile's LDG with compute, per-column loop over smem-broadcast paths.

#define N_BATCH 16384
#define ROWS    16
#define RPT     4
#define NT      (ROWS / RPT)
#define TPB     320
#define PREP_T  1024
#define MAX_OUT 2048
#define P_SMEM  512
#define NSORT   512
#define KMAX    4      // prefetch covers rep_dim <= KMAX*TPB

__device__ uint4 g_paths[P_SMEM];     // binned + canonically sorted {r1,r2,cg,deg}
__device__ uint2 g_colinfo[MAX_OUT];  // {start | ns<<16, eff}

__device__ __forceinline__ int block_incl_scan(int v, int tid, int bd) {
    __shared__ int ws[32];
    int lane = tid & 31, wid = tid >> 5;
    __syncthreads();
    #pragma unroll
    for (int d = 1; d < 32; d <<= 1) {
        int t = __shfl_up_sync(0xffffffffu, v, d);
        if (lane >= d) v += t;
    }
    if (lane == 31) ws[wid] = v;
    __syncthreads();
    if (wid == 0) {
        int w = (lane < (bd >> 5)) ? ws[lane] : 0;
        #pragma unroll
        for (int d = 1; d < 32; d <<= 1) {
            int t = __shfl_up_sync(0xffffffffu, w, d);
            if (lane >= d) w += t;
        }
        ws[lane] = w;
    }
    __syncthreads();
    return v + (wid > 0 ? ws[wid - 1] : 0);
}

__global__ void prep_kernel(const void* r1v, const void* r2v, const void* rov,
                            const float* __restrict__ cg, int M, int out_dim) {
    __shared__ int   sp[NSORT + 1];       // ordered run-start positions
    __shared__ uint4 praw[NSORT];         // paths in position order
    __shared__ int   pro[NSORT];
    __shared__ uint4 pbin[P_SMEM];        // binned + sorted
    __shared__ int   cnt[MAX_OUT], stt[MAX_OUT], cur[MAX_OUT];
    __shared__ int   s_is64, s_carry;
    int tid = threadIdx.x, bd = blockDim.x;

    // dtype auto-detect: int64 little-endian small values -> odd words all zero
    if (tid < 32) {
        const unsigned* w = (const unsigned*)r1v;
        int nw = M < 512 ? M : 512;
        int bad = 0;
        for (int i = 1 + 2 * tid; i < nw; i += 64) bad |= (w[i] != 0u);
        unsigned any = __ballot_sync(0xffffffffu, bad != 0);
        if (tid == 0) { s_is64 = (any == 0u); s_carry = 0; }
    }
    __syncthreads();
    // 32-bit low-word access (values small, little-endian): stride 2 if int64
    int sh = s_is64 ? 1 : 0;
    const int*      A1  = (const int*)r1v;
    const int*      A2  = (const int*)r2v;
    const int*      AO  = (const int*)rov;
    const unsigned* cgu = (const unsigned*)cg;
    #define IDX1(m) A1[(m) << sh]
    #define IDX2(m) A2[(m) << sh]
    #define IDXO(m) AO[(m) << sh]
    #define ISSTART(m) ((m) == 0 || \
        !(IDX1((m) - 1) + 1 == IDX1(m) && IDX2((m) - 1) + 1 == IDX2(m) && \
          IDXO((m) - 1) + 1 == IDXO(m) && cgu[(m) - 1] == cgu[m]))

    // ---- Phase A: ordered compaction of run starts, coalesced rounds ----
    for (int base = 0; base < M; base += bd) {
        int m = base + tid;
        int f = (m < M) ? (ISSTART(m) ? 1 : 0) : 0;
        int incl = block_incl_scan(f, tid, bd);
        int carry = s_carry;
        if (f) {
            int pid = carry + incl - 1;
            if (pid < NSORT) sp[pid] = m;
        }
        __syncthreads();
        if (tid == bd - 1) s_carry = carry + incl;
        __syncthreads();
    }
    int P = s_carry;
    if (P > NSORT) P = NSORT;                  // safety; expected P ~ 150
    if (tid == 0) sp[P] = M;
    __syncthreads();

    // ---- Phase B: materialize paths in position order ----
    for (int p = tid; p < P; p += bd) {
        int s = sp[p];
        praw[p] = make_uint4((unsigned)IDX1(s), (unsigned)IDX2(s),
                             cgu[s], (unsigned)(sp[p + 1] - s));
        pro[p] = IDXO(s);
    }
    for (int i = tid; i < out_dim; i += bd) cnt[i] = 0;
    for (int i = tid; i < P_SMEM; i += bd) pbin[i] = make_uint4(0u, 0u, 0u, 0u);
    __syncthreads();

    // ---- Phase C: bin by ro_0, exclusive scan, scatter ----
    for (int p = tid; p < P; p += bd) atomicAdd(&cnt[pro[p]], 1);
    __syncthreads();
    {
        int CH = (out_dim + bd - 1) / bd;
        int cb = tid * CH;
        int local = 0;
        for (int i = 0; i < CH; i++) { int idx = cb + i; if (idx < out_dim) local += cnt[idx]; }
        int incl = block_incl_scan(local, tid, bd);
        int run = incl - local;
        for (int i = 0; i < CH; i++) {
            int idx = cb + i;
            if (idx < out_dim) { stt[idx] = run; cur[idx] = run; run += cnt[idx]; }
        }
    }
    __syncthreads();
    for (int p = tid; p < P; p += bd) {
        int pos = atomicAdd(&cur[pro[p]], 1);
        pbin[pos] = praw[p];
    }
    __syncthreads();

    // ---- Phase D: canonical in-bin insertion sort (deg DESC, r1, r2) ----
    for (int b = tid; b < out_dim; b += bd) {
        int c0 = cnt[b];
        if (c0 > 1) {
            int s0 = stt[b];
            for (int i = 1; i < c0; i++) {
                uint4 key = pbin[s0 + i];
                int j = i - 1;
                while (j >= 0) {
                    uint4 q = pbin[s0 + j];
                    bool keyFirst = (key.w > q.w) ||
                                    (key.w == q.w && (key.x < q.x ||
                                     (key.x == q.x && key.y < q.y)));
                    if (!keyFirst) break;
                    pbin[s0 + j + 1] = q;
                    j--;
                }
                pbin[s0 + j + 1] = key;
            }
        }
    }
    __syncthreads();

    // ---- Phase E: per-column info + coalesced write-out ----
    for (int c = tid; c < out_dim; c += bd) {
        int b = c;
        while (b >= 0 && cnt[b] == 0) b--;
        uint2 info = make_uint2(0u, 0u);
        if (b >= 0) {
            int c0 = cnt[b], s0 = stt[b], ns = c - b, eff = 0;
            while (eff < c0 && (int)pbin[s0 + eff].w > ns) eff++;
            if (eff > 0)
                info = make_uint2((unsigned)s0 | ((unsigned)ns << 16), (unsigned)eff);
        }
        g_colinfo[c] = info;
    }
    for (int i = tid; i < P_SMEM; i += bd) g_paths[i] = pbin[i];
    #undef ISSTART
    #undef IDX1
    #undef IDX2
    #undef IDXO
}

// ===== couple: R5 exact (best measured 43.3us) =====
__global__ void __launch_bounds__(TPB)
couple_kernel(const float* __restrict__ x1, const float* __restrict__ x2,
              float* __restrict__ out, int rep_dim, int out_dim) {
    extern __shared__ char smraw[];
    float4* x1s = (float4*)smraw;              // rep_dim float4 (4 rows interleaved)
    float4* x2s = x1s + rep_dim;
    uint2*  ci  = (uint2*)(x2s + rep_dim);     // out_dim
    uint4*  pts = (uint4*)(ci + ((out_dim + 1) & ~1));  // P_SMEM paths

    int tid = threadIdx.x;
    for (int i = tid; i < P_SMEM; i += TPB) pts[i] = g_paths[i];
    for (int i = tid; i < out_dim; i += TPB) ci[i] = g_colinfo[i];

    int row0 = blockIdx.x * ROWS;

    // stage tile 0 directly
    {
        const float* a0 = x1 + (size_t)row0 * rep_dim;
        const float* b0 = x2 + (size_t)row0 * rep_dim;
        for (int i = tid; i < rep_dim; i += TPB) {
            x1s[i] = make_float4(a0[i], a0[i + rep_dim], a0[i + 2 * rep_dim], a0[i + 3 * rep_dim]);
            x2s[i] = make_float4(b0[i], b0[i + rep_dim], b0[i + 2 * rep_dim], b0[i + 3 * rep_dim]);
        }
    }
    __syncthreads();

    for (int t = 0; t < NT; t++) {
        int r = row0 + t * RPT;

        // prefetch next subtile into registers (LDG in flight during compute)
        float4 pa[KMAX], pb[KMAX];
        if (t + 1 < NT) {
            const float* a0 = x1 + (size_t)(r + RPT) * rep_dim;
            const float* b0 = x2 + (size_t)(r + RPT) * rep_dim;
            #pragma unroll
            for (int k = 0; k < KMAX; k++) {
                int i = tid + k * TPB;
                if (i < rep_dim) {
                    pa[k] = make_float4(a0[i], a0[i + rep_dim], a0[i + 2 * rep_dim], a0[i + 3 * rep_dim]);
                    pb[k] = make_float4(b0[i], b0[i + rep_dim], b0[i + 2 * rep_dim], b0[i + 3 * rep_dim]);
                }
            }
        }

        // compute current subtile
        for (int o = tid; o < out_dim; o += TPB) {
            uint2 c = ci[o];
            int s = (int)(c.x & 0xffffu);
            unsigned ns = c.x >> 16;
            int ne = (int)c.y;
            float4 acc = make_float4(0.f, 0.f, 0.f, 0.f);
            #pragma unroll 2
            for (int j = 0; j < ne; j++) {
                uint4 p = pts[s + j];                // warp-uniform: broadcast
                float cgv = __uint_as_float(p.z);
                float4 A = x1s[p.x + ns];            // lane-consecutive: conflict-free
                float4 B = x2s[p.y + ns];
                acc.x = fmaf(A.x * B.x, cgv, acc.x);
                acc.y = fmaf(A.y * B.y, cgv, acc.y);
                acc.z = fmaf(A.z * B.z, cgv, acc.z);
                acc.w = fmaf(A.w * B.w, cgv, acc.w);
            }
            float* ob = out + (size_t)r * out_dim + o;
            ob[0]                   = acc.x;
            ob[(size_t)out_dim]     = acc.y;
            ob[(size_t)out_dim * 2] = acc.z;
            ob[(size_t)out_dim * 3] = acc.w;
        }
        __syncthreads();   // everyone done reading the buffer

        if (t + 1 < NT) {
            #pragma unroll
            for (int k = 0; k < KMAX; k++) {
                int i = tid + k * TPB;
                if (i < rep_dim) { x1s[i] = pa[k]; x2s[i] = pb[k]; }
            }
            __syncthreads();   // buffer ready for next subtile
        }
    }
}

extern "C" void kernel_launch(void* const* d_in, const int* in_sizes, int n_in,
                              void* d_out, int out_size) {
    const float* x1 = (const float*)d_in[0];
    const float* x2 = (const float*)d_in[1];
    const float* cg = (const float*)d_in[2];
    const void*  r1 = d_in[3];
    const void*  r2 = d_in[4];
    const void*  ro = d_in[5];
    int M = in_sizes[2];
    int rep_dim = in_sizes[0] / N_BATCH;
    int out_dim = out_size / N_BATCH;

    prep_kernel<<<1, PREP_T>>>(r1, r2, ro, cg, M, out_dim);

    size_t smem = (size_t)rep_dim * 32 + (size_t)((out_dim + 1) & ~1) * 8
                + (size_t)P_SMEM * 16;
    cudaFuncSetAttribute(couple_kernel,
                         cudaFuncAttributeMaxDynamicSharedMemorySize, 160 * 1024);
    couple_kernel<<<N_BATCH / ROWS, TPB, smem>>>(x1, x2, (float*)d_out,
                                                 rep_dim, out_dim);
}